// round 8
// baseline (speedup 1.0000x reference)
#include <cuda_runtime.h>
#include <math.h>

typedef unsigned long long ull;

#define EMBD   300
#define UNITS  512
#define BATCH  64
#define TLEN   512
#define NC     3072   // 2 * 3 * UNITS

// scan decomposition: 128 blocks = 2 dir x 2 batch-halves x 32 unit-slabs
#define UPB    16     // units per block
#define BPG    32     // batches per group

// ---------------- scratch (device globals; no allocations allowed) ----------
__device__ float g_xw[(size_t)TLEN * NC * BATCH];          // [t][c][b]
__device__ float g_h[2 * 2 * 2 * UNITS * BPG];             // [dir][bgrp][par][k][b32]

struct alignas(128) BarWord { unsigned int v; unsigned int pad[31]; };
__device__ BarWord g_cnt[4];
__device__ BarWord g_gen[4];

// ---------------- packed fp32x2 helpers -------------------------------------
__device__ __forceinline__ ull pk2(float lo, float hi) {
    ull r; asm("mov.b64 %0, {%1, %2};" : "=l"(r) : "f"(lo), "f"(hi)); return r;
}
__device__ __forceinline__ void fma2(ull& d, ull a, ull b) {
    asm("fma.rn.f32x2 %0, %1, %2, %0;" : "+l"(d) : "l"(a), "l"(b));
}
__device__ __forceinline__ ull add2(ull a, ull b) {
    ull r; asm("add.rn.f32x2 %0, %1, %2;" : "=l"(r) : "l"(a), "l"(b)); return r;
}
__device__ __forceinline__ float2 upk2(ull v) {
    float2 r; asm("mov.b64 {%0, %1}, %2;" : "=f"(r.x), "=f"(r.y) : "l"(v)); return r;
}

// ---------------- Kernel 1: embed gather + input GEMM, double-buffered ------
// dyn smem: As[2][16][64] | Bs[2][16][128] | Cs[128][65]
#define EG_SMEM ((2*16*64 + 2*16*128 + 128*65) * 4)   // 57856 B
__global__ __launch_bounds__(256, 2) void embed_gemm(
    const int* __restrict__ tokens, const float* __restrict__ emb,
    const float* __restrict__ Wf, const float* __restrict__ Wb,
    const float* __restrict__ bf, const float* __restrict__ bb)
{
    extern __shared__ float dsm[];
    float* As = dsm;               // [buf][kk][b]
    float* Bs = As + 2 * 16 * 64;  // [buf][kk][c]
    float* Cs = Bs + 2 * 16 * 128; // [c][b] pad 65

    const int t   = blockIdx.y;
    const int c0  = blockIdx.x * 128;
    const int tid = threadIdx.x;
    const int tx  = tid & 15;
    const int ty  = tid >> 4;

    const int arow = tid >> 2;
    const int akk  = (tid & 3) * 4;
    const int tok  = tokens[(size_t)arow * TLEN + t];
    const float* aptr = emb + (size_t)tok * EMBD;

    const int brow = tid >> 4;
    const int bcol = (tid & 15) * 8;
    const bool fwd = (c0 < 1536);
    const float* W   = fwd ? Wf : Wb;
    const int    wc0 = fwd ? c0 : (c0 - 1536);

    const int NT = (EMBD + 15) / 16;   // 19

    float ar_[4];
    float br_[8];

    // prologue: load tile 0 into regs then smem buf 0
    {
        #pragma unroll
        for (int i = 0; i < 4; i++) {
            int k = akk + i;
            ar_[i] = (k < EMBD) ? __ldg(aptr + k) : 0.f;
        }
        const float* wp = W + (size_t)brow * 1536 + wc0 + bcol;
        *(float4*)br_       = *(const float4*)wp;
        *(float4*)(br_ + 4) = *(const float4*)(wp + 4);
        #pragma unroll
        for (int i = 0; i < 4; i++) As[(akk + i) * 64 + arow] = ar_[i];
        *(float4*)&Bs[brow * 128 + bcol]     = *(float4*)br_;
        *(float4*)&Bs[brow * 128 + bcol + 4] = *(float4*)(br_ + 4);
    }
    __syncthreads();

    ull acc2[4][4];
    #pragma unroll
    for (int i = 0; i < 4; i++)
        #pragma unroll
        for (int j = 0; j < 4; j++) acc2[i][j] = 0ull;

    for (int kt = 0; kt < NT; kt++) {
        const int cur = kt & 1;
        // prefetch next tile into regs (DRAM latency hidden under compute)
        if (kt + 1 < NT) {
            const int k0 = (kt + 1) * 16;
            #pragma unroll
            for (int i = 0; i < 4; i++) {
                int k = k0 + akk + i;
                ar_[i] = (k < EMBD) ? __ldg(aptr + k) : 0.f;
            }
            int k = k0 + brow;
            if (k < EMBD) {
                const float* wp = W + (size_t)k * 1536 + wc0 + bcol;
                *(float4*)br_       = *(const float4*)wp;
                *(float4*)(br_ + 4) = *(const float4*)(wp + 4);
            } else {
                *(float4*)br_       = make_float4(0, 0, 0, 0);
                *(float4*)(br_ + 4) = make_float4(0, 0, 0, 0);
            }
        }
        // compute on buf cur
        const float* Ab = As + cur * 1024;
        const float* Bb = Bs + cur * 2048;
        #pragma unroll
        for (int kk = 0; kk < 16; kk++) {
            const float4 a4 = *(const float4*)(Ab + kk * 64 + ty * 4);
            const float4 b0 = *(const float4*)(Bb + kk * 128 + tx * 8);
            const float4 b1 = *(const float4*)(Bb + kk * 128 + tx * 8 + 4);
            const ull bp[4] = {pk2(b0.x, b0.y), pk2(b0.z, b0.w),
                               pk2(b1.x, b1.y), pk2(b1.z, b1.w)};
            const float av[4] = {a4.x, a4.y, a4.z, a4.w};
            #pragma unroll
            for (int i = 0; i < 4; i++) {
                const ull ad = pk2(av[i], av[i]);
                #pragma unroll
                for (int j = 0; j < 4; j++) fma2(acc2[i][j], ad, bp[j]);
            }
        }
        // stage next tile to smem buf nxt
        if (kt + 1 < NT) {
            const int nxt = cur ^ 1;
            float* An = As + nxt * 1024;
            float* Bn = Bs + nxt * 2048;
            #pragma unroll
            for (int i = 0; i < 4; i++) An[(akk + i) * 64 + arow] = ar_[i];
            *(float4*)&Bn[brow * 128 + bcol]     = *(float4*)br_;
            *(float4*)&Bn[brow * 128 + bcol + 4] = *(float4*)(br_ + 4);
        }
        __syncthreads();
    }

    const float* bias = fwd ? bf : bb;
    #pragma unroll
    for (int j = 0; j < 4; j++) {
        const float2 bv = make_float2(bias[wc0 + tx * 8 + j * 2],
                                      bias[wc0 + tx * 8 + j * 2 + 1]);
        #pragma unroll
        for (int i = 0; i < 4; i++) {
            const float2 v = upk2(acc2[i][j]);
            Cs[(tx * 8 + j * 2) * 65 + ty * 4 + i]     = v.x + bv.x;
            Cs[(tx * 8 + j * 2 + 1) * 65 + ty * 4 + i] = v.y + bv.y;
        }
    }
    __syncthreads();

    {   // coalesced store: g_xw[t][c0+cl][b]
        const int cl  = tid >> 1;
        const int bb0 = (tid & 1) * 32;
        float* dst = g_xw + ((size_t)t * NC + c0 + cl) * BATCH + bb0;
        #pragma unroll
        for (int j = 0; j < 32; j += 4) {
            float4 v = make_float4(Cs[cl * 65 + bb0 + j], Cs[cl * 65 + bb0 + j + 1],
                                   Cs[cl * 65 + bb0 + j + 2], Cs[cl * 65 + bb0 + j + 3]);
            *(float4*)(dst + j) = v;
        }
    }
}

// ---------------- split per-group barrier (32 blocks) ------------------------
__device__ __forceinline__ void bar_arrive(int gid, int nblk)
{
    __syncthreads();                      // all h stores issued
    if (threadIdx.x == 0) {
        __threadfence();                  // release
        unsigned int my = atomicAdd(&g_cnt[gid].v, 1u);
        if (my == (unsigned)nblk - 1u) {
            *(volatile unsigned int*)&g_cnt[gid].v = 0u;
            __threadfence();
            atomicAdd(&g_gen[gid].v, 1u);
        }
    }
}
__device__ __forceinline__ void bar_wait(int gid, unsigned int gen0)
{
    if (threadIdx.x == 0) {
        while (*(volatile unsigned int*)&g_gen[gid].v == gen0) { }
        __threadfence();                  // acquire
    }
    __syncthreads();
}

// ---------------- Kernel 2: persistent bidirectional GRU scan ---------------
// 256 threads. Warp w: k in [w*64, w*64+64); lane halves split k 32/32 and
// pair-reduce via shfl. Per thread tile: 4 units x 8 batches x 3 gates.
// smem: Us[512][48] | hs[512][32] | part[8][3][32][18]
__global__ __launch_bounds__(256, 1) void gru_scan(
    const float* __restrict__ Uf, const float* __restrict__ Ub,
    const float* __restrict__ bf, const float* __restrict__ bb,
    float* __restrict__ out)
{
    extern __shared__ float sm[];
    float* Us   = sm;                    // 24576 floats (96KB)
    float* hs   = Us + 512 * 48;         // 16384 floats (64KB)
    float* part = hs + 512 * 32;         // 8*3*576 = 13824 floats (54KB)
    __shared__ float brec[48];

    const int tid  = threadIdx.x;
    const int bid  = blockIdx.x;
    const int dir  = bid >> 6;
    const int bgrp = (bid >> 5) & 1;
    const int us   = bid & 31;
    const int gid  = dir * 2 + bgrp;
    const int u0   = us * UPB;
    const int B0   = bgrp * BPG;

    const float* U    = dir ? Ub : Uf;
    const float* brow = (dir ? bb : bf) + 1536;

    // U slab: Us[k][g*16+ui] = U[k][g*512 + u0 + ui]
    for (int l = tid; l < 512 * 48; l += 256) {
        int k = l / 48, j = l % 48;
        int g = j >> 4, ui = j & 15;
        Us[l] = U[(size_t)k * 1536 + g * 512 + u0 + ui];
    }
    if (tid < 48) brec[tid] = brow[(tid >> 4) * 512 + u0 + (tid & 15)];

    // zero h ping-pong: 131072 floats over 32768 threads -> 4 each
    {
        int l = (bid * 256 + tid) * 4;
        *(float4*)(g_h + l) = make_float4(0.f, 0.f, 0.f, 0.f);
    }
    unsigned int gen = *(volatile unsigned int*)&g_gen[gid].v;
    bar_arrive(gid, 32);
    bar_wait(gid, gen);
    gen++;

    // matvec tiling
    const int wrp   = tid >> 5;            // 0..7 -> k base wrp*64
    const int lane  = tid & 31;
    const int khalf = lane >> 4;           // 0/1 -> +0 / +32 k
    const int sub   = lane & 15;
    const int uh    = sub & 3;             // units uh*4..uh*4+3
    const int bg    = sub >> 2;            // batches bg*8..bg*8+7
    const int kbase = wrp * 64 + khalf * 32;

    // combine mapping: 2 outputs per thread
    const int cu2 = tid & 7;               // unit pair cu2*2, cu2*2+1
    const int cb  = tid >> 3;              // batch 0..31

    // xw prefetch for step 0
    float xg[6];
    {
        const int t0 = dir ? (TLEN - 1) : 0;
        const float* xp = g_xw + ((size_t)t0 * NC + dir * 1536 + u0 + cu2 * 2) * BATCH
                          + B0 + cb;
        #pragma unroll
        for (int g = 0; g < 3; g++) {
            xg[g * 2]     = __ldg(xp + (size_t)g * 512 * BATCH);
            xg[g * 2 + 1] = __ldg(xp + ((size_t)g * 512 + 1) * BATCH);
        }
    }

    for (int s = 0; s < TLEN; s++) {
        const int p = s & 1;
        const int t = dir ? (TLEN - 1 - s) : s;

        // stage h_old slice [k][b32]: 4096 float4, 16 per thread
        {
            const float4* hg4 = (const float4*)(g_h +
                ((size_t)gid * 2 + p) * UNITS * BPG);
            float4* hs4 = (float4*)hs;
            #pragma unroll
            for (int l = tid; l < UNITS * BPG / 4; l += 256) hs4[l] = __ldg(hg4 + l);
        }
        __syncthreads();

        // matvec: 4 units x 8 batches x 3 gates over 32 k (48 fma2 per k)
        ull az[2][8], ar[2][8], ah[2][8];
        #pragma unroll
        for (int i = 0; i < 2; i++)
            #pragma unroll
            for (int j = 0; j < 8; j++) { az[i][j] = ar[i][j] = ah[i][j] = 0ull; }
        {
            const float* hp = hs + (size_t)kbase * 32 + bg * 8;
            const float* up = Us + (size_t)kbase * 48 + uh * 4;
            #pragma unroll 2
            for (int k = 0; k < 32; k++) {
                const float4 hA = *(const float4*)(hp + k * 32);
                const float4 hB = *(const float4*)(hp + k * 32 + 4);
                const float4 z4 = *(const float4*)(up + k * 48);
                const float4 r4 = *(const float4*)(up + k * 48 + 16);
                const float4 q4 = *(const float4*)(up + k * 48 + 32);
                const ull zd0 = pk2(z4.x, z4.y), zd1 = pk2(z4.z, z4.w);
                const ull rd0 = pk2(r4.x, r4.y), rd1 = pk2(r4.z, r4.w);
                const ull qd0 = pk2(q4.x, q4.y), qd1 = pk2(q4.z, q4.w);
                const float hv[8] = {hA.x, hA.y, hA.z, hA.w,
                                     hB.x, hB.y, hB.z, hB.w};
                #pragma unroll
                for (int b = 0; b < 8; b++) {
                    const ull hd = pk2(hv[b], hv[b]);
                    fma2(az[0][b], zd0, hd); fma2(az[1][b], zd1, hd);
                    fma2(ar[0][b], rd0, hd); fma2(ar[1][b], rd1, hd);
                    fma2(ah[0][b], qd0, hd); fma2(ah[1][b], qd1, hd);
                }
            }
        }
        // pairwise k-half reduction within warp (partner lane ^ 16)
        #pragma unroll
        for (int i = 0; i < 2; i++)
            #pragma unroll
            for (int b = 0; b < 8; b++) {
                az[i][b] = add2(az[i][b], __shfl_xor_sync(0xffffffffu, az[i][b], 16));
                ar[i][b] = add2(ar[i][b], __shfl_xor_sync(0xffffffffu, ar[i][b], 16));
                ah[i][b] = add2(ah[i][b], __shfl_xor_sync(0xffffffffu, ah[i][b], 16));
            }
        // store partials: half 0 stores batches +0..3, half 1 stores +4..7
        {
            const int bsel = khalf * 4;
            float* pb = part + wrp * 1728 + (bg * 8 + bsel) * 18 + uh * 4;
            #pragma unroll
            for (int b = 0; b < 4; b++) {
                float* pp = pb + b * 18;
                *(ull*)(pp)            = az[0][bsel + b];
                *(ull*)(pp + 2)        = az[1][bsel + b];
                *(ull*)(pp + 576)      = ar[0][bsel + b];
                *(ull*)(pp + 576 + 2)  = ar[1][bsel + b];
                *(ull*)(pp + 1152)     = ah[0][bsel + b];
                *(ull*)(pp + 1152 + 2) = ah[1][bsel + b];
            }
        }
        __syncthreads();

        // combine: units cu2*2, cu2*2+1; batch cb
        float hn0, hn1;
        {
            float rz0 = brec[cu2 * 2],      rz1 = brec[cu2 * 2 + 1];
            float rr0 = brec[16 + cu2 * 2], rr1 = brec[16 + cu2 * 2 + 1];
            float rh0 = brec[32 + cu2 * 2], rh1 = brec[32 + cu2 * 2 + 1];
            #pragma unroll
            for (int q = 0; q < 8; q++) {
                const float* pq = part + q * 1728 + cb * 18 + cu2 * 2;
                float2 v;
                v = upk2(*(const ull*)(pq));        rz0 += v.x; rz1 += v.y;
                v = upk2(*(const ull*)(pq + 576));  rr0 += v.x; rr1 += v.y;
                v = upk2(*(const ull*)(pq + 1152)); rh0 += v.x; rh1 += v.y;
            }
            const float h0 = hs[(u0 + cu2 * 2) * 32 + cb];
            const float h1 = hs[(u0 + cu2 * 2 + 1) * 32 + cb];

            const float z0 = 1.f / (1.f + expf(-(xg[0] + rz0)));
            const float z1 = 1.f / (1.f + expf(-(xg[1] + rz1)));
            const float r0 = 1.f / (1.f + expf(-(xg[2] + rr0)));
            const float r1 = 1.f / (1.f + expf(-(xg[3] + rr1)));
            const float c0 = tanhf(xg[4] + r0 * rh0);
            const float c1 = tanhf(xg[5] + r1 * rh1);
            hn0 = z0 * h0 + (1.f - z0) * c0;
            hn1 = z1 * h1 + (1.f - z1) * c1;

            float* hw = g_h + ((size_t)gid * 2 + (p ^ 1)) * UNITS * BPG;
            hw[(u0 + cu2 * 2) * 32 + cb]     = hn0;
            hw[(u0 + cu2 * 2 + 1) * 32 + cb] = hn1;
        }
        bar_arrive(gid, 32);   // h published

        // ---- latency cover between arrive and wait ----
        {
            float2 o2 = make_float2(hn0, hn1);
            *(float2*)(out + ((size_t)(B0 + cb) * TLEN + t) * 1024
                           + dir * 512 + u0 + cu2 * 2) = o2;
            if (s == TLEN - 1)
                *(float2*)(out + (size_t)BATCH * TLEN * 1024
                               + (size_t)(B0 + cb) * 1024
                               + dir * 512 + u0 + cu2 * 2) = o2;
        }
        if (s + 1 < TLEN) {   // prefetch xw for next step
            const int tn = dir ? (TLEN - 2 - s) : (s + 1);
            const float* xp = g_xw + ((size_t)tn * NC + dir * 1536 + u0 + cu2 * 2) * BATCH
                              + B0 + cb;
            #pragma unroll
            for (int g = 0; g < 3; g++) {
                xg[g * 2]     = __ldg(xp + (size_t)g * 512 * BATCH);
                xg[g * 2 + 1] = __ldg(xp + ((size_t)g * 512 + 1) * BATCH);
            }
        }
        bar_wait(gid, gen);
        gen++;
    }
}

// ---------------- launch ----------------------------------------------------
extern "C" void kernel_launch(void* const* d_in, const int* in_sizes, int n_in,
                              void* d_out, int out_size)
{
    const int*   tokens = (const int*)  d_in[0];
    const float* emb    = (const float*)d_in[1];
    const float* W_f    = (const float*)d_in[2];
    const float* U_f    = (const float*)d_in[3];
    const float* b_f    = (const float*)d_in[4];
    const float* W_b    = (const float*)d_in[5];
    const float* U_b    = (const float*)d_in[6];
    const float* b_b    = (const float*)d_in[7];
    float* out = (float*)d_out;

    (void)in_sizes; (void)n_in; (void)out_size;

    cudaFuncSetAttribute(embed_gemm, cudaFuncAttributeMaxDynamicSharedMemorySize,
                         EG_SMEM);
    dim3 g1(NC / 128, TLEN);
    embed_gemm<<<g1, 256, EG_SMEM>>>(tokens, emb, W_f, W_b, b_f, b_b);

    const size_t smem = (512 * 48 + 512 * 32 + 24 * 576) * sizeof(float); // 219136
    cudaFuncSetAttribute(gru_scan, cudaFuncAttributeMaxDynamicSharedMemorySize,
                         (int)smem);
    gru_scan<<<128, 256, smem>>>(U_f, U_b, b_f, b_b, out);
}

// round 10
// speedup vs baseline: 1.1022x; 1.1022x over previous
#include <cuda_runtime.h>
#include <math.h>

typedef unsigned long long ull;

#define EMBD   300
#define UNITS  512
#define BATCH  64
#define TLEN   512
#define NC     3072   // 2 * 3 * UNITS

// scan decomposition: 128 blocks = 2 dir x 2 batch-halves x 32 unit-slabs
#define UPB    16     // units per block
#define BPG    32     // batches per group

// ---------------- scratch (device globals; no allocations allowed) ----------
__device__ float g_xw[(size_t)TLEN * NC * BATCH];          // [t][c][b]
__device__ float g_h[2 * 2 * 2 * UNITS * BPG];             // [dir][bgrp][par][k][b32]

struct alignas(128) BarWord { unsigned int v; unsigned int pad[31]; };
__device__ BarWord g_cnt[4];
__device__ BarWord g_gen[4];

// ---------------- packed fp32x2 helpers -------------------------------------
__device__ __forceinline__ ull pk2(float lo, float hi) {
    ull r; asm("mov.b64 %0, {%1, %2};" : "=l"(r) : "f"(lo), "f"(hi)); return r;
}
__device__ __forceinline__ void fma2(ull& d, ull a, ull b) {
    asm("fma.rn.f32x2 %0, %1, %2, %0;" : "+l"(d) : "l"(a), "l"(b));
}
__device__ __forceinline__ ull add2(ull a, ull b) {
    ull r; asm("add.rn.f32x2 %0, %1, %2;" : "=l"(r) : "l"(a), "l"(b)); return r;
}
__device__ __forceinline__ float2 upk2(ull v) {
    float2 r; asm("mov.b64 {%0, %1}, %2;" : "=f"(r.x), "=f"(r.y) : "l"(v)); return r;
}

// ---------------- Kernel 1: embed gather + input GEMM, double-buffered ------
#define EG_SMEM ((2*16*64 + 2*16*128 + 128*65) * 4)   // 57856 B
__global__ __launch_bounds__(256, 2) void embed_gemm(
    const int* __restrict__ tokens, const float* __restrict__ emb,
    const float* __restrict__ Wf, const float* __restrict__ Wb,
    const float* __restrict__ bf, const float* __restrict__ bb)
{
    extern __shared__ float dsm[];
    float* As = dsm;               // [buf][kk][b]
    float* Bs = As + 2 * 16 * 64;  // [buf][kk][c]
    float* Cs = Bs + 2 * 16 * 128; // [c][b] pad 65

    const int t   = blockIdx.y;
    const int c0  = blockIdx.x * 128;
    const int tid = threadIdx.x;
    const int tx  = tid & 15;
    const int ty  = tid >> 4;

    const int arow = tid >> 2;
    const int akk  = (tid & 3) * 4;
    const int tok  = tokens[(size_t)arow * TLEN + t];
    const float* aptr = emb + (size_t)tok * EMBD;

    const int brow = tid >> 4;
    const int bcol = (tid & 15) * 8;
    const bool fwd = (c0 < 1536);
    const float* W   = fwd ? Wf : Wb;
    const int    wc0 = fwd ? c0 : (c0 - 1536);

    const int NT = (EMBD + 15) / 16;   // 19

    float ar_[4];
    float br_[8];

    {
        #pragma unroll
        for (int i = 0; i < 4; i++) {
            int k = akk + i;
            ar_[i] = (k < EMBD) ? __ldg(aptr + k) : 0.f;
        }
        const float* wp = W + (size_t)brow * 1536 + wc0 + bcol;
        *(float4*)br_       = *(const float4*)wp;
        *(float4*)(br_ + 4) = *(const float4*)(wp + 4);
        #pragma unroll
        for (int i = 0; i < 4; i++) As[(akk + i) * 64 + arow] = ar_[i];
        *(float4*)&Bs[brow * 128 + bcol]     = *(float4*)br_;
        *(float4*)&Bs[brow * 128 + bcol + 4] = *(float4*)(br_ + 4);
    }
    __syncthreads();

    ull acc2[4][4];
    #pragma unroll
    for (int i = 0; i < 4; i++)
        #pragma unroll
        for (int j = 0; j < 4; j++) acc2[i][j] = 0ull;

    for (int kt = 0; kt < NT; kt++) {
        const int cur = kt & 1;
        if (kt + 1 < NT) {
            const int k0 = (kt + 1) * 16;
            #pragma unroll
            for (int i = 0; i < 4; i++) {
                int k = k0 + akk + i;
                ar_[i] = (k < EMBD) ? __ldg(aptr + k) : 0.f;
            }
            int k = k0 + brow;
            if (k < EMBD) {
                const float* wp = W + (size_t)k * 1536 + wc0 + bcol;
                *(float4*)br_       = *(const float4*)wp;
                *(float4*)(br_ + 4) = *(const float4*)(wp + 4);
            } else {
                *(float4*)br_       = make_float4(0, 0, 0, 0);
                *(float4*)(br_ + 4) = make_float4(0, 0, 0, 0);
            }
        }
        const float* Ab = As + cur * 1024;
        const float* Bb = Bs + cur * 2048;
        #pragma unroll
        for (int kk = 0; kk < 16; kk++) {
            const float4 a4 = *(const float4*)(Ab + kk * 64 + ty * 4);
            const float4 b0 = *(const float4*)(Bb + kk * 128 + tx * 8);
            const float4 b1 = *(const float4*)(Bb + kk * 128 + tx * 8 + 4);
            const ull bp[4] = {pk2(b0.x, b0.y), pk2(b0.z, b0.w),
                               pk2(b1.x, b1.y), pk2(b1.z, b1.w)};
            const float av[4] = {a4.x, a4.y, a4.z, a4.w};
            #pragma unroll
            for (int i = 0; i < 4; i++) {
                const ull ad = pk2(av[i], av[i]);
                #pragma unroll
                for (int j = 0; j < 4; j++) fma2(acc2[i][j], ad, bp[j]);
            }
        }
        if (kt + 1 < NT) {
            const int nxt = cur ^ 1;
            float* An = As + nxt * 1024;
            float* Bn = Bs + nxt * 2048;
            #pragma unroll
            for (int i = 0; i < 4; i++) An[(akk + i) * 64 + arow] = ar_[i];
            *(float4*)&Bn[brow * 128 + bcol]     = *(float4*)br_;
            *(float4*)&Bn[brow * 128 + bcol + 4] = *(float4*)(br_ + 4);
        }
        __syncthreads();
    }

    const float* bias = fwd ? bf : bb;
    #pragma unroll
    for (int j = 0; j < 4; j++) {
        const float2 bv = make_float2(bias[wc0 + tx * 8 + j * 2],
                                      bias[wc0 + tx * 8 + j * 2 + 1]);
        #pragma unroll
        for (int i = 0; i < 4; i++) {
            const float2 v = upk2(acc2[i][j]);
            Cs[(tx * 8 + j * 2) * 65 + ty * 4 + i]     = v.x + bv.x;
            Cs[(tx * 8 + j * 2 + 1) * 65 + ty * 4 + i] = v.y + bv.y;
        }
    }
    __syncthreads();

    {   // coalesced store: g_xw[t][c0+cl][b]
        const int cl  = tid >> 1;
        const int bb0 = (tid & 1) * 32;
        float* dst = g_xw + ((size_t)t * NC + c0 + cl) * BATCH + bb0;
        #pragma unroll
        for (int j = 0; j < 32; j += 4) {
            float4 v = make_float4(Cs[cl * 65 + bb0 + j], Cs[cl * 65 + bb0 + j + 1],
                                   Cs[cl * 65 + bb0 + j + 2], Cs[cl * 65 + bb0 + j + 3]);
            *(float4*)(dst + j) = v;
        }
    }
}

// ---------------- split per-group barrier (32 blocks) ------------------------
__device__ __forceinline__ void bar_arrive(int gid, int nblk)
{
    __syncthreads();
    if (threadIdx.x == 0) {
        __threadfence();                  // release
        unsigned int my = atomicAdd(&g_cnt[gid].v, 1u);
        if (my == (unsigned)nblk - 1u) {
            *(volatile unsigned int*)&g_cnt[gid].v = 0u;
            __threadfence();
            atomicAdd(&g_gen[gid].v, 1u);
        }
    }
}
__device__ __forceinline__ void bar_wait(int gid, unsigned int gen0)
{
    if (threadIdx.x == 0) {
        while (*(volatile unsigned int*)&g_gen[gid].v == gen0) { }
        __threadfence();                  // acquire
    }
    __syncthreads();
}

// ---------------- Kernel 2: persistent bidirectional GRU scan ---------------
// 512 threads, 16 warps. Warp pair (2j,2j+1) covers k window [j*64, j*64+64):
// lane halves take 32 k each (shfl-reduced), warp parity selects batch half.
// Per-thread tile: 4 units x 4 batches x 3 gates over 32 k (R7's 24 accums).
// smem: Us[512][48] | hs[512][32] | part[8][3][32][18]
__global__ __launch_bounds__(512, 1) void gru_scan(
    const float* __restrict__ Uf, const float* __restrict__ Ub,
    const float* __restrict__ bf, const float* __restrict__ bb,
    float* __restrict__ out)
{
    extern __shared__ float sm[];
    float* Us   = sm;                    // 24576 floats (96KB)
    float* hs   = Us + 512 * 48;         // 16384 floats (64KB)
    float* part = hs + 512 * 32;         // 8*3*576 = 13824 floats (54KB)
    __shared__ float brec[48];

    const int tid  = threadIdx.x;
    const int bid  = blockIdx.x;
    const int dir  = bid >> 6;
    const int bgrp = (bid >> 5) & 1;
    const int us   = bid & 31;
    const int gid  = dir * 2 + bgrp;
    const int u0   = us * UPB;
    const int B0   = bgrp * BPG;

    const float* U    = dir ? Ub : Uf;
    const float* brow = (dir ? bb : bf) + 1536;

    // U slab: Us[k][g*16+ui] = U[k][g*512 + u0 + ui]
    for (int l = tid; l < 512 * 48; l += 512) {
        int k = l / 48, j = l % 48;
        int g = j >> 4, ui = j & 15;
        Us[l] = U[(size_t)k * 1536 + g * 512 + u0 + ui];
    }
    if (tid < 48) brec[tid] = brow[(tid >> 4) * 512 + u0 + (tid & 15)];

    // zero h ping-pong: 131072 floats over 65536 threads -> 2 each
    {
        int l = (bid * 512 + tid) * 2;
        *(float2*)(g_h + l) = make_float2(0.f, 0.f);
    }
    unsigned int gen = *(volatile unsigned int*)&g_gen[gid].v;
    bar_arrive(gid, 32);
    bar_wait(gid, gen);
    gen++;

    // matvec tiling
    const int wrp   = tid >> 5;                     // 0..15
    const int lane  = tid & 31;
    const int kj    = wrp >> 1;                     // k window 0..7 (64 k)
    const int khalf = lane >> 4;                    // 0/1 -> +0 / +32
    const int sub   = lane & 15;
    const int uh    = sub & 3;                      // units uh*4..uh*4+3
    const int bgsel = (sub >> 2) | ((wrp & 1) << 2);// 0..7 -> batches bgsel*4..+3
    const int kbase = kj * 64 + khalf * 32;

    // combine mapping: 1 output per thread
    const int cu = tid & 15;             // local unit
    const int cb = tid >> 4;             // batch 0..31

    // xw prefetch for step 0
    float xg[3];
    {
        const int t0 = dir ? (TLEN - 1) : 0;
        const float* xp = g_xw + ((size_t)t0 * NC + dir * 1536 + u0 + cu) * BATCH
                          + B0 + cb;
        #pragma unroll
        for (int g = 0; g < 3; g++)
            xg[g] = __ldg(xp + (size_t)g * 512 * BATCH);
    }

    for (int s = 0; s < TLEN; s++) {
        const int p = s & 1;
        const int t = dir ? (TLEN - 1 - s) : s;

        // stage h_old slice [k][b32]: 4096 float4, 8 per thread
        {
            const float4* hg4 = (const float4*)(g_h +
                ((size_t)gid * 2 + p) * UNITS * BPG);
            float4* hs4 = (float4*)hs;
            #pragma unroll
            for (int l = tid; l < UNITS * BPG / 4; l += 512) hs4[l] = __ldg(hg4 + l);
        }
        __syncthreads();

        // matvec: 4 units x 4 batches x 3 gates over 32 k
        ull az[2][4], ar[2][4], ah[2][4];
        #pragma unroll
        for (int i = 0; i < 2; i++)
            #pragma unroll
            for (int j = 0; j < 4; j++) { az[i][j] = ar[i][j] = ah[i][j] = 0ull; }
        {
            const float* hp = hs + (size_t)kbase * 32 + bgsel * 4;
            const float* up = Us + (size_t)kbase * 48 + uh * 4;
            #pragma unroll 4
            for (int k = 0; k < 32; k++) {
                const float4 h4 = *(const float4*)(hp + k * 32);
                const float4 z4 = *(const float4*)(up + k * 48);
                const float4 r4 = *(const float4*)(up + k * 48 + 16);
                const float4 q4 = *(const float4*)(up + k * 48 + 32);
                const ull hd[4] = {pk2(h4.x, h4.x), pk2(h4.y, h4.y),
                                   pk2(h4.z, h4.z), pk2(h4.w, h4.w)};
                const ull z0 = pk2(z4.x, z4.y), z1 = pk2(z4.z, z4.w);
                const ull r0 = pk2(r4.x, r4.y), r1 = pk2(r4.z, r4.w);
                const ull q0 = pk2(q4.x, q4.y), q1 = pk2(q4.z, q4.w);
                #pragma unroll
                for (int b = 0; b < 4; b++) {
                    fma2(az[0][b], z0, hd[b]); fma2(az[1][b], z1, hd[b]);
                    fma2(ar[0][b], r0, hd[b]); fma2(ar[1][b], r1, hd[b]);
                    fma2(ah[0][b], q0, hd[b]); fma2(ah[1][b], q1, hd[b]);
                }
            }
        }
        // k-half pair reduction within warp (partner lane ^ 16)
        #pragma unroll
        for (int i = 0; i < 2; i++)
            #pragma unroll
            for (int b = 0; b < 4; b++) {
                az[i][b] = add2(az[i][b], __shfl_xor_sync(0xffffffffu, az[i][b], 16));
                ar[i][b] = add2(ar[i][b], __shfl_xor_sync(0xffffffffu, ar[i][b], 16));
                ah[i][b] = add2(ah[i][b], __shfl_xor_sync(0xffffffffu, ah[i][b], 16));
            }
        // store partials: khalf 0 stores batches +0..1, khalf 1 stores +2..3
        {
            const int bsel = khalf * 2;
            float* pb = part + kj * 1728 + (bgsel * 4 + bsel) * 18 + uh * 4;
            #pragma unroll
            for (int b = 0; b < 2; b++) {
                float* pp = pb + b * 18;
                *(ull*)(pp)            = az[0][bsel + b];
                *(ull*)(pp + 2)        = az[1][bsel + b];
                *(ull*)(pp + 576)      = ar[0][bsel + b];
                *(ull*)(pp + 576 + 2)  = ar[1][bsel + b];
                *(ull*)(pp + 1152)     = ah[0][bsel + b];
                *(ull*)(pp + 1152 + 2) = ah[1][bsel + b];
            }
        }
        __syncthreads();

        // combine: unit cu, batch cb — one h_new per thread
        float hn;
        {
            float rz = brec[cu], rr = brec[16 + cu], rh = brec[32 + cu];
            #pragma unroll
            for (int q = 0; q < 8; q++) {
                const float* pq = part + q * 1728 + cb * 18 + cu;
                rz += pq[0];
                rr += pq[576];
                rh += pq[1152];
            }
            const float hold = hs[(u0 + cu) * 32 + cb];

            const float z  = 1.f / (1.f + expf(-(xg[0] + rz)));
            const float rg = 1.f / (1.f + expf(-(xg[1] + rr)));
            const float hh = tanhf(xg[2] + rg * rh);
            hn = z * hold + (1.f - z) * hh;

            float* hw = g_h + ((size_t)gid * 2 + (p ^ 1)) * UNITS * BPG;
            hw[(u0 + cu) * 32 + cb] = hn;
        }
        bar_arrive(gid, 32);   // h published

        // ---- latency cover between arrive and wait ----
        out[((size_t)(B0 + cb) * TLEN + t) * 1024 + dir * 512 + u0 + cu] = hn;
        if (s == TLEN - 1)
            out[(size_t)BATCH * TLEN * 1024 + (size_t)(B0 + cb) * 1024
                + dir * 512 + u0 + cu] = hn;
        if (s + 1 < TLEN) {   // prefetch xw for next step
            const int tn = dir ? (TLEN - 2 - s) : (s + 1);
            const float* xp = g_xw + ((size_t)tn * NC + dir * 1536 + u0 + cu) * BATCH
                              + B0 + cb;
            #pragma unroll
            for (int g = 0; g < 3; g++)
                xg[g] = __ldg(xp + (size_t)g * 512 * BATCH);
        }
        bar_wait(gid, gen);
        gen++;
    }
}

// ---------------- launch ----------------------------------------------------
extern "C" void kernel_launch(void* const* d_in, const int* in_sizes, int n_in,
                              void* d_out, int out_size)
{
    const int*   tokens = (const int*)  d_in[0];
    const float* emb    = (const float*)d_in[1];
    const float* W_f    = (const float*)d_in[2];
    const float* U_f    = (const float*)d_in[3];
    const float* b_f    = (const float*)d_in[4];
    const float* W_b    = (const float*)d_in[5];
    const float* U_b    = (const float*)d_in[6];
    const float* b_b    = (const float*)d_in[7];
    float* out = (float*)d_out;

    (void)in_sizes; (void)n_in; (void)out_size;

    cudaFuncSetAttribute(embed_gemm, cudaFuncAttributeMaxDynamicSharedMemorySize,
                         EG_SMEM);
    dim3 g1(NC / 128, TLEN);
    embed_gemm<<<g1, 256, EG_SMEM>>>(tokens, emb, W_f, W_b, b_f, b_b);

    const size_t smem = (512 * 48 + 512 * 32 + 24 * 576) * sizeof(float); // 219136
    cudaFuncSetAttribute(gru_scan, cudaFuncAttributeMaxDynamicSharedMemorySize,
                         (int)smem);
    gru_scan<<<128, 512, smem>>>(U_f, U_b, b_f, b_b, out);
}

// round 11
// speedup vs baseline: 1.4347x; 1.3017x over previous
#include <cuda_runtime.h>
#include <math.h>

typedef unsigned long long ull;

#define EMBD   300
#define UNITS  512
#define BATCH  64
#define TLEN   512
#define NC     3072   // 2 * 3 * UNITS

// scan decomposition: 128 blocks = 2 dir x 2 batch-halves x 32 unit-slabs
#define UPB    16     // units per block
#define BPG    32     // batches per group

// ---------------- scratch (device globals; no allocations allowed) ----------
__device__ float g_xw[(size_t)TLEN * NC * BATCH];          // [t][c][b]
__device__ float g_h[2 * 2 * 2 * UNITS * BPG];             // [dir][bgrp][par][k][b32]

struct alignas(128) BarWord { unsigned int v; unsigned int pad[31]; };
__device__ BarWord g_cnt[4];
__device__ BarWord g_gen[4];

// ---------------- packed fp32x2 helpers -------------------------------------
__device__ __forceinline__ ull pk2(float lo, float hi) {
    ull r; asm("mov.b64 %0, {%1, %2};" : "=l"(r) : "f"(lo), "f"(hi)); return r;
}
__device__ __forceinline__ void fma2(ull& d, ull a, ull b) {
    asm("fma.rn.f32x2 %0, %1, %2, %0;" : "+l"(d) : "l"(a), "l"(b));
}
__device__ __forceinline__ float2 upk2(ull v) {
    float2 r; asm("mov.b64 {%0, %1}, %2;" : "=f"(r.x), "=f"(r.y) : "l"(v)); return r;
}

// ---------------- Kernel 1: embed gather + input GEMM -----------------------
// 64 rows (batch) x 256 cols per block; 8x8 per thread; double-buffered.
// No transpose smem: per-column 32B register stores (sector-exact).
#define EG_SMEM ((2*16*64 + 2*16*256) * 4)   // 40960 B
__global__ __launch_bounds__(256, 2) void embed_gemm(
    const int* __restrict__ tokens, const float* __restrict__ emb,
    const float* __restrict__ Wf, const float* __restrict__ Wb,
    const float* __restrict__ bf, const float* __restrict__ bb)
{
    extern __shared__ float dsm[];
    float* As = dsm;               // [buf][kk][64]
    float* Bs = As + 2 * 16 * 64;  // [buf][kk][256]

    const int t   = blockIdx.y;
    const int c0  = blockIdx.x * 256;          // 1536-boundary aligned (6 blocks/dir)
    const int tid = threadIdx.x;
    const int tx  = tid & 31;                  // col group: 8 cols at tx*8
    const int ty  = tid >> 5;                  // row group: 8 rows at ty*8

    // A loader: one batch row, 4 contiguous k
    const int arow = tid >> 2;
    const int akk  = (tid & 3) * 4;
    const int tok  = tokens[(size_t)arow * TLEN + t];
    const float* aptr = emb + (size_t)tok * EMBD;

    // B loader: row kk = tid>>4, 16 cols at (tid&15)*16
    const int bkk = tid >> 4;
    const int bc0 = (tid & 15) * 16;
    const bool fwd = (c0 < 1536);
    const float* W   = fwd ? Wf : Wb;
    const int    wc0 = fwd ? c0 : (c0 - 1536);

    const int NT = (EMBD + 15) / 16;   // 19

    float ar_[4];
    float br_[16];

    // prologue: tile 0 -> regs -> smem buf 0
    {
        #pragma unroll
        for (int i = 0; i < 4; i++) {
            int k = akk + i;
            ar_[i] = (k < EMBD) ? __ldg(aptr + k) : 0.f;
        }
        const float* wp = W + (size_t)bkk * 1536 + wc0 + bc0;
        #pragma unroll
        for (int j = 0; j < 4; j++)
            *(float4*)(br_ + j * 4) = *(const float4*)(wp + j * 4);
        #pragma unroll
        for (int i = 0; i < 4; i++) As[(akk + i) * 64 + arow] = ar_[i];
        #pragma unroll
        for (int j = 0; j < 4; j++)
            *(float4*)&Bs[bkk * 256 + bc0 + j * 4] = *(float4*)(br_ + j * 4);
    }
    __syncthreads();

    ull acc[8][4];
    #pragma unroll
    for (int i = 0; i < 8; i++)
        #pragma unroll
        for (int j = 0; j < 4; j++) acc[i][j] = 0ull;

    for (int kt = 0; kt < NT; kt++) {
        const int cur = kt & 1;
        if (kt + 1 < NT) {
            const int k0 = (kt + 1) * 16;
            #pragma unroll
            for (int i = 0; i < 4; i++) {
                int k = k0 + akk + i;
                ar_[i] = (k < EMBD) ? __ldg(aptr + k) : 0.f;
            }
            int k = k0 + bkk;
            if (k < EMBD) {
                const float* wp = W + (size_t)k * 1536 + wc0 + bc0;
                #pragma unroll
                for (int j = 0; j < 4; j++)
                    *(float4*)(br_ + j * 4) = *(const float4*)(wp + j * 4);
            } else {
                #pragma unroll
                for (int j = 0; j < 4; j++)
                    *(float4*)(br_ + j * 4) = make_float4(0, 0, 0, 0);
            }
        }
        const float* Ab = As + cur * 1024;
        const float* Bb = Bs + cur * 4096;
        #pragma unroll
        for (int kk = 0; kk < 16; kk++) {
            const float4 a0 = *(const float4*)(Ab + kk * 64 + ty * 8);
            const float4 a1 = *(const float4*)(Ab + kk * 64 + ty * 8 + 4);
            const ulonglong2 b01 = *(const ulonglong2*)(Bb + kk * 256 + tx * 8);
            const ulonglong2 b23 = *(const ulonglong2*)(Bb + kk * 256 + tx * 8 + 4);
            const ull bp[4] = {b01.x, b01.y, b23.x, b23.y};
            const float av[8] = {a0.x, a0.y, a0.z, a0.w, a1.x, a1.y, a1.z, a1.w};
            #pragma unroll
            for (int i = 0; i < 8; i++) {
                const ull ad = pk2(av[i], av[i]);
                #pragma unroll
                for (int j = 0; j < 4; j++) fma2(acc[i][j], ad, bp[j]);
            }
        }
        if (kt + 1 < NT) {
            const int nxt = cur ^ 1;
            float* An = As + nxt * 1024;
            float* Bn = Bs + nxt * 4096;
            #pragma unroll
            for (int i = 0; i < 4; i++) An[(akk + i) * 64 + arow] = ar_[i];
            #pragma unroll
            for (int j = 0; j < 4; j++)
                *(float4*)&Bn[bkk * 256 + bc0 + j * 4] = *(float4*)(br_ + j * 4);
        }
        __syncthreads();
    }

    // bias + direct store: thread owns cols tx*8+{0..7}, rows ty*8..ty*8+7
    const float* bias = fwd ? bf : bb;
    #pragma unroll
    for (int j = 0; j < 4; j++) {           // col pair 2j, 2j+1
        const int ce = tx * 8 + j * 2;
        const float be = bias[wc0 + ce];
        const float bo = bias[wc0 + ce + 1];
        float ve[8], vo[8];
        #pragma unroll
        for (int i = 0; i < 8; i++) {
            const float2 v = upk2(acc[i][j]);
            ve[i] = v.x + be;
            vo[i] = v.y + bo;
        }
        float* de = g_xw + ((size_t)t * NC + c0 + ce) * BATCH + ty * 8;
        float* doo = de + BATCH;
        *(float4*)(de)      = make_float4(ve[0], ve[1], ve[2], ve[3]);
        *(float4*)(de + 4)  = make_float4(ve[4], ve[5], ve[6], ve[7]);
        *(float4*)(doo)     = make_float4(vo[0], vo[1], vo[2], vo[3]);
        *(float4*)(doo + 4) = make_float4(vo[4], vo[5], vo[6], vo[7]);
    }
}

// ---------------- split per-group barrier (32 blocks) ------------------------
__device__ __forceinline__ void bar_arrive(int gid, int nblk)
{
    __syncthreads();
    if (threadIdx.x == 0) {
        __threadfence();                  // release
        unsigned int my = atomicAdd(&g_cnt[gid].v, 1u);
        if (my == (unsigned)nblk - 1u) {
            *(volatile unsigned int*)&g_cnt[gid].v = 0u;
            __threadfence();
            atomicAdd(&g_gen[gid].v, 1u);
        }
    }
}
__device__ __forceinline__ void bar_wait(int gid, unsigned int gen0)
{
    if (threadIdx.x == 0) {
        while (*(volatile unsigned int*)&g_gen[gid].v == gen0) { }
        __threadfence();                  // acquire
    }
    __syncthreads();
}

// ---------------- Kernel 2: persistent bidirectional GRU scan (R7 tile) -----
// 256 threads. Warp w: k in [w*64, w*64+64); lanes uh(4) x bg(8).
// Per-thread: 4 units x 4 batches x 3 gates. U loaded as ulonglong2 (no repack).
// smem: Us[512][48] | hs[512][32] | part[8][3][32][18]
__global__ __launch_bounds__(256, 1) void gru_scan(
    const float* __restrict__ Uf, const float* __restrict__ Ub,
    const float* __restrict__ bf, const float* __restrict__ bb,
    float* __restrict__ out)
{
    extern __shared__ float sm[];
    float* Us   = sm;                    // 24576 floats (96KB)
    float* hs   = Us + 512 * 48;         // 16384 floats (64KB)
    float* part = hs + 512 * 32;         // 8*3*576 = 13824 floats (54KB)
    __shared__ float brec[48];

    const int tid  = threadIdx.x;
    const int bid  = blockIdx.x;
    const int dir  = bid >> 6;
    const int bgrp = (bid >> 5) & 1;
    const int us   = bid & 31;
    const int gid  = dir * 2 + bgrp;
    const int u0   = us * UPB;
    const int B0   = bgrp * BPG;

    const float* U    = dir ? Ub : Uf;
    const float* brow = (dir ? bb : bf) + 1536;

    // U slab: Us[k][g*16+ui] = U[k][g*512 + u0 + ui]
    for (int l = tid; l < 512 * 48; l += 256) {
        int k = l / 48, j = l % 48;
        int g = j >> 4, ui = j & 15;
        Us[l] = U[(size_t)k * 1536 + g * 512 + u0 + ui];
    }
    if (tid < 48) brec[tid] = brow[(tid >> 4) * 512 + u0 + (tid & 15)];

    // zero h ping-pong
    {
        int l = (bid * 256 + tid) * 4;
        *(float4*)(g_h + l) = make_float4(0.f, 0.f, 0.f, 0.f);
    }
    unsigned int gen = *(volatile unsigned int*)&g_gen[gid].v;
    bar_arrive(gid, 32);
    bar_wait(gid, gen);
    gen++;

    // matvec tiling: warp = kh (8 warps x 64 k); lanes: uh(4) x bg(8)
    const int kh = tid >> 5;
    const int uh = tid & 3;              // units uh*4..uh*4+3
    const int bg = (tid >> 2) & 7;       // batches bg*4..bg*4+3

    // combine mapping: 2 outputs per thread
    const int cu2 = tid & 7;             // unit pair cu2*2, cu2*2+1
    const int cb  = tid >> 3;            // batch 0..31

    // xw prefetch for step 0
    float xg[6];
    {
        const int t0 = dir ? (TLEN - 1) : 0;
        const float* xp = g_xw + ((size_t)t0 * NC + dir * 1536 + u0 + cu2 * 2) * BATCH
                          + B0 + cb;
        #pragma unroll
        for (int g = 0; g < 3; g++) {
            xg[g * 2]     = __ldg(xp + (size_t)g * 512 * BATCH);
            xg[g * 2 + 1] = __ldg(xp + ((size_t)g * 512 + 1) * BATCH);
        }
    }

    for (int s = 0; s < TLEN; s++) {
        const int p = s & 1;
        const int t = dir ? (TLEN - 1 - s) : s;

        // stage h_old slice [k][b32]: 4096 float4, 16 per thread
        {
            const float4* hg4 = (const float4*)(g_h +
                ((size_t)gid * 2 + p) * UNITS * BPG);
            float4* hs4 = (float4*)hs;
            #pragma unroll
            for (int l = tid; l < UNITS * BPG / 4; l += 256) hs4[l] = __ldg(hg4 + l);
        }
        __syncthreads();

        // matvec: 4 units x 4 batches x 3 gates over 64 k (24 fma2 per k)
        ull az[2][4], ar[2][4], ah[2][4];
        #pragma unroll
        for (int i = 0; i < 2; i++)
            #pragma unroll
            for (int j = 0; j < 4; j++) { az[i][j] = ar[i][j] = ah[i][j] = 0ull; }
        {
            const float* hp = hs + (size_t)kh * 64 * 32 + bg * 4;
            const float* up = Us + (size_t)kh * 64 * 48 + uh * 4;
            #pragma unroll 2
            for (int k = 0; k < 64; k++) {
                const float4 h4 = *(const float4*)(hp + k * 32);
                const ulonglong2 z2 = *(const ulonglong2*)(up + k * 48);
                const ulonglong2 r2 = *(const ulonglong2*)(up + k * 48 + 16);
                const ulonglong2 q2 = *(const ulonglong2*)(up + k * 48 + 32);
                const ull hd[4] = {pk2(h4.x, h4.x), pk2(h4.y, h4.y),
                                   pk2(h4.z, h4.z), pk2(h4.w, h4.w)};
                #pragma unroll
                for (int b = 0; b < 4; b++) {
                    fma2(az[0][b], z2.x, hd[b]); fma2(az[1][b], z2.y, hd[b]);
                    fma2(ar[0][b], r2.x, hd[b]); fma2(ar[1][b], r2.y, hd[b]);
                    fma2(ah[0][b], q2.x, hd[b]); fma2(ah[1][b], q2.y, hd[b]);
                }
            }
        }
        // part[(kh*3+g)*576 + b*18 + u]
        {
            #pragma unroll
            for (int b = 0; b < 4; b++) {
                float* pb = part + kh * 3 * 576 + (bg * 4 + b) * 18 + uh * 4;
                *(ull*)(pb)            = az[0][b];
                *(ull*)(pb + 2)        = az[1][b];
                *(ull*)(pb + 576)      = ar[0][b];
                *(ull*)(pb + 576 + 2)  = ar[1][b];
                *(ull*)(pb + 1152)     = ah[0][b];
                *(ull*)(pb + 1152 + 2) = ah[1][b];
            }
        }
        __syncthreads();

        // combine: units cu2*2, cu2*2+1; batch cb
        float hn0, hn1;
        {
            float rz0 = brec[cu2 * 2],      rz1 = brec[cu2 * 2 + 1];
            float rr0 = brec[16 + cu2 * 2], rr1 = brec[16 + cu2 * 2 + 1];
            float rh0 = brec[32 + cu2 * 2], rh1 = brec[32 + cu2 * 2 + 1];
            #pragma unroll
            for (int q = 0; q < 8; q++) {
                const float* pq = part + q * 3 * 576 + cb * 18 + cu2 * 2;
                float2 v;
                v = upk2(*(const ull*)(pq));        rz0 += v.x; rz1 += v.y;
                v = upk2(*(const ull*)(pq + 576));  rr0 += v.x; rr1 += v.y;
                v = upk2(*(const ull*)(pq + 1152)); rh0 += v.x; rh1 += v.y;
            }
            const float h0 = hs[(u0 + cu2 * 2) * 32 + cb];
            const float h1 = hs[(u0 + cu2 * 2 + 1) * 32 + cb];

            const float z0 = 1.f / (1.f + expf(-(xg[0] + rz0)));
            const float z1 = 1.f / (1.f + expf(-(xg[1] + rz1)));
            const float r0 = 1.f / (1.f + expf(-(xg[2] + rr0)));
            const float r1 = 1.f / (1.f + expf(-(xg[3] + rr1)));
            const float c0 = tanhf(xg[4] + r0 * rh0);
            const float c1 = tanhf(xg[5] + r1 * rh1);
            hn0 = z0 * h0 + (1.f - z0) * c0;
            hn1 = z1 * h1 + (1.f - z1) * c1;

            float* hw = g_h + ((size_t)gid * 2 + (p ^ 1)) * UNITS * BPG;
            hw[(u0 + cu2 * 2) * 32 + cb]     = hn0;
            hw[(u0 + cu2 * 2 + 1) * 32 + cb] = hn1;
        }
        bar_arrive(gid, 32);   // h published

        // ---- latency cover between arrive and wait ----
        {
            float2 o2 = make_float2(hn0, hn1);
            *(float2*)(out + ((size_t)(B0 + cb) * TLEN + t) * 1024
                           + dir * 512 + u0 + cu2 * 2) = o2;
            if (s == TLEN - 1)
                *(float2*)(out + (size_t)BATCH * TLEN * 1024
                               + (size_t)(B0 + cb) * 1024
                               + dir * 512 + u0 + cu2 * 2) = o2;
        }
        if (s + 1 < TLEN) {   // prefetch xw for next step
            const int tn = dir ? (TLEN - 2 - s) : (s + 1);
            const float* xp = g_xw + ((size_t)tn * NC + dir * 1536 + u0 + cu2 * 2) * BATCH
                              + B0 + cb;
            #pragma unroll
            for (int g = 0; g < 3; g++) {
                xg[g * 2]     = __ldg(xp + (size_t)g * 512 * BATCH);
                xg[g * 2 + 1] = __ldg(xp + ((size_t)g * 512 + 1) * BATCH);
            }
        }
        bar_wait(gid, gen);
        gen++;
    }
}

// ---------------- launch ----------------------------------------------------
extern "C" void kernel_launch(void* const* d_in, const int* in_sizes, int n_in,
                              void* d_out, int out_size)
{
    const int*   tokens = (const int*)  d_in[0];
    const float* emb    = (const float*)d_in[1];
    const float* W_f    = (const float*)d_in[2];
    const float* U_f    = (const float*)d_in[3];
    const float* b_f    = (const float*)d_in[4];
    const float* W_b    = (const float*)d_in[5];
    const float* U_b    = (const float*)d_in[6];
    const float* b_b    = (const float*)d_in[7];
    float* out = (float*)d_out;

    (void)in_sizes; (void)n_in; (void)out_size;

    cudaFuncSetAttribute(embed_gemm, cudaFuncAttributeMaxDynamicSharedMemorySize,
                         EG_SMEM);
    dim3 g1(NC / 256, TLEN);
    embed_gemm<<<g1, 256, EG_SMEM>>>(tokens, emb, W_f, W_b, b_f, b_b);

    const size_t smem = (512 * 48 + 512 * 32 + 24 * 576) * sizeof(float); // 219136
    cudaFuncSetAttribute(gru_scan, cudaFuncAttributeMaxDynamicSharedMemorySize,
                         (int)smem);
    gru_scan<<<128, 256, smem>>>(U_f, U_b, b_f, b_b, out);
}

// round 12
// speedup vs baseline: 1.4419x; 1.0050x over previous
#include <cuda_runtime.h>
#include <math.h>

typedef unsigned long long ull;

#define EMBD   300
#define UNITS  512
#define BATCH  64
#define TLEN   512
#define NC     3072   // 2 * 3 * UNITS

// scan decomposition: 128 blocks = 2 dir x 2 batch-halves x 32 unit-slabs
#define UPB    16     // units per block
#define BPG    32     // batches per group

// ---------------- scratch (device globals; no allocations allowed) ----------
__device__ float g_xw[(size_t)TLEN * NC * BATCH];          // [t][c][b]
__device__ float g_h[2 * 2 * 2 * UNITS * BPG];             // [dir][bgrp][par][k][b32]

struct alignas(128) BarWord { unsigned int v; unsigned int pad[31]; };
__device__ BarWord g_cnt[4];
__device__ BarWord g_gen[4];

// ---------------- packed fp32x2 helpers -------------------------------------
__device__ __forceinline__ ull pk2(float lo, float hi) {
    ull r; asm("mov.b64 %0, {%1, %2};" : "=l"(r) : "f"(lo), "f"(hi)); return r;
}
__device__ __forceinline__ void fma2(ull& d, ull a, ull b) {
    asm("fma.rn.f32x2 %0, %1, %2, %0;" : "+l"(d) : "l"(a), "l"(b));
}
__device__ __forceinline__ float2 upk2(ull v) {
    float2 r; asm("mov.b64 {%0, %1}, %2;" : "=f"(r.x), "=f"(r.y) : "l"(v)); return r;
}

// ---------------- Kernel 1: embed gather + input GEMM (R11, unchanged) ------
#define EG_SMEM ((2*16*64 + 2*16*256) * 4)   // 40960 B
__global__ __launch_bounds__(256, 2) void embed_gemm(
    const int* __restrict__ tokens, const float* __restrict__ emb,
    const float* __restrict__ Wf, const float* __restrict__ Wb,
    const float* __restrict__ bf, const float* __restrict__ bb)
{
    extern __shared__ float dsm[];
    float* As = dsm;               // [buf][kk][64]
    float* Bs = As + 2 * 16 * 64;  // [buf][kk][256]

    const int t   = blockIdx.y;
    const int c0  = blockIdx.x * 256;
    const int tid = threadIdx.x;
    const int tx  = tid & 31;
    const int ty  = tid >> 5;

    const int arow = tid >> 2;
    const int akk  = (tid & 3) * 4;
    const int tok  = tokens[(size_t)arow * TLEN + t];
    const float* aptr = emb + (size_t)tok * EMBD;

    const int bkk = tid >> 4;
    const int bc0 = (tid & 15) * 16;
    const bool fwd = (c0 < 1536);
    const float* W   = fwd ? Wf : Wb;
    const int    wc0 = fwd ? c0 : (c0 - 1536);

    const int NT = (EMBD + 15) / 16;   // 19

    float ar_[4];
    float br_[16];

    {
        #pragma unroll
        for (int i = 0; i < 4; i++) {
            int k = akk + i;
            ar_[i] = (k < EMBD) ? __ldg(aptr + k) : 0.f;
        }
        const float* wp = W + (size_t)bkk * 1536 + wc0 + bc0;
        #pragma unroll
        for (int j = 0; j < 4; j++)
            *(float4*)(br_ + j * 4) = *(const float4*)(wp + j * 4);
        #pragma unroll
        for (int i = 0; i < 4; i++) As[(akk + i) * 64 + arow] = ar_[i];
        #pragma unroll
        for (int j = 0; j < 4; j++)
            *(float4*)&Bs[bkk * 256 + bc0 + j * 4] = *(float4*)(br_ + j * 4);
    }
    __syncthreads();

    ull acc[8][4];
    #pragma unroll
    for (int i = 0; i < 8; i++)
        #pragma unroll
        for (int j = 0; j < 4; j++) acc[i][j] = 0ull;

    for (int kt = 0; kt < NT; kt++) {
        const int cur = kt & 1;
        if (kt + 1 < NT) {
            const int k0 = (kt + 1) * 16;
            #pragma unroll
            for (int i = 0; i < 4; i++) {
                int k = k0 + akk + i;
                ar_[i] = (k < EMBD) ? __ldg(aptr + k) : 0.f;
            }
            int k = k0 + bkk;
            if (k < EMBD) {
                const float* wp = W + (size_t)k * 1536 + wc0 + bc0;
                #pragma unroll
                for (int j = 0; j < 4; j++)
                    *(float4*)(br_ + j * 4) = *(const float4*)(wp + j * 4);
            } else {
                #pragma unroll
                for (int j = 0; j < 4; j++)
                    *(float4*)(br_ + j * 4) = make_float4(0, 0, 0, 0);
            }
        }
        const float* Ab = As + cur * 1024;
        const float* Bb = Bs + cur * 4096;
        #pragma unroll
        for (int kk = 0; kk < 16; kk++) {
            const float4 a0 = *(const float4*)(Ab + kk * 64 + ty * 8);
            const float4 a1 = *(const float4*)(Ab + kk * 64 + ty * 8 + 4);
            const ulonglong2 b01 = *(const ulonglong2*)(Bb + kk * 256 + tx * 8);
            const ulonglong2 b23 = *(const ulonglong2*)(Bb + kk * 256 + tx * 8 + 4);
            const ull bp[4] = {b01.x, b01.y, b23.x, b23.y};
            const float av[8] = {a0.x, a0.y, a0.z, a0.w, a1.x, a1.y, a1.z, a1.w};
            #pragma unroll
            for (int i = 0; i < 8; i++) {
                const ull ad = pk2(av[i], av[i]);
                #pragma unroll
                for (int j = 0; j < 4; j++) fma2(acc[i][j], ad, bp[j]);
            }
        }
        if (kt + 1 < NT) {
            const int nxt = cur ^ 1;
            float* An = As + nxt * 1024;
            float* Bn = Bs + nxt * 4096;
            #pragma unroll
            for (int i = 0; i < 4; i++) An[(akk + i) * 64 + arow] = ar_[i];
            #pragma unroll
            for (int j = 0; j < 4; j++)
                *(float4*)&Bn[bkk * 256 + bc0 + j * 4] = *(float4*)(br_ + j * 4);
        }
        __syncthreads();
    }

    const float* bias = fwd ? bf : bb;
    #pragma unroll
    for (int j = 0; j < 4; j++) {
        const int ce = tx * 8 + j * 2;
        const float be = bias[wc0 + ce];
        const float bo = bias[wc0 + ce + 1];
        float ve[8], vo[8];
        #pragma unroll
        for (int i = 0; i < 8; i++) {
            const float2 v = upk2(acc[i][j]);
            ve[i] = v.x + be;
            vo[i] = v.y + bo;
        }
        float* de = g_xw + ((size_t)t * NC + c0 + ce) * BATCH + ty * 8;
        float* doo = de + BATCH;
        *(float4*)(de)      = make_float4(ve[0], ve[1], ve[2], ve[3]);
        *(float4*)(de + 4)  = make_float4(ve[4], ve[5], ve[6], ve[7]);
        *(float4*)(doo)     = make_float4(vo[0], vo[1], vo[2], vo[3]);
        *(float4*)(doo + 4) = make_float4(vo[4], vo[5], vo[6], vo[7]);
    }
}

// ---------------- split per-group barrier (32 blocks) ------------------------
__device__ __forceinline__ void bar_arrive(int gid, int nblk)
{
    __syncthreads();
    if (threadIdx.x == 0) {
        __threadfence();                  // release
        unsigned int my = atomicAdd(&g_cnt[gid].v, 1u);
        if (my == (unsigned)nblk - 1u) {
            *(volatile unsigned int*)&g_cnt[gid].v = 0u;
            __threadfence();
            atomicAdd(&g_gen[gid].v, 1u);
        }
    }
}
__device__ __forceinline__ void bar_wait(int gid, unsigned int gen0)
{
    if (threadIdx.x == 0) {
        while (*(volatile unsigned int*)&g_gen[gid].v == gen0) { }
        __threadfence();                  // acquire
    }
    __syncthreads();
}

// ---------------- Kernel 2: persistent bidirectional GRU scan ---------------
// 256 threads. h read straight from g_h (L2) with 8-deep LDG batching — no
// smem staging. U from smem as ulonglong2. Tile: 4u x 4b x 3 gates over 64 k.
// smem: Us[512][48] | part[8][3][32][18]
__global__ __launch_bounds__(256, 1) void gru_scan(
    const float* __restrict__ Uf, const float* __restrict__ Ub,
    const float* __restrict__ bf, const float* __restrict__ bb,
    float* __restrict__ out)
{
    extern __shared__ float sm[];
    float* Us   = sm;                    // 24576 floats (96KB)
    float* part = Us + 512 * 48;         // 8*3*576 = 13824 floats (54KB)
    __shared__ float brec[48];

    const int tid  = threadIdx.x;
    const int bid  = blockIdx.x;
    const int dir  = bid >> 6;
    const int bgrp = (bid >> 5) & 1;
    const int us   = bid & 31;
    const int gid  = dir * 2 + bgrp;
    const int u0   = us * UPB;
    const int B0   = bgrp * BPG;

    const float* U    = dir ? Ub : Uf;
    const float* brow = (dir ? bb : bf) + 1536;

    // U slab: Us[k][g*16+ui] = U[k][g*512 + u0 + ui]
    for (int l = tid; l < 512 * 48; l += 256) {
        int k = l / 48, j = l % 48;
        int g = j >> 4, ui = j & 15;
        Us[l] = U[(size_t)k * 1536 + g * 512 + u0 + ui];
    }
    if (tid < 48) brec[tid] = brow[(tid >> 4) * 512 + u0 + (tid & 15)];

    // zero h ping-pong
    {
        int l = (bid * 256 + tid) * 4;
        *(float4*)(g_h + l) = make_float4(0.f, 0.f, 0.f, 0.f);
    }
    unsigned int gen = *(volatile unsigned int*)&g_gen[gid].v;
    bar_arrive(gid, 32);
    bar_wait(gid, gen);
    gen++;

    // matvec tiling: warp = kh (8 warps x 64 k); lanes: uh(4) x bg(8)
    const int kh = tid >> 5;
    const int uh = tid & 3;              // units uh*4..uh*4+3
    const int bg = (tid >> 2) & 7;       // batches bg*4..bg*4+3

    // combine mapping: 2 outputs per thread
    const int cu2 = tid & 7;             // unit pair cu2*2, cu2*2+1
    const int cb  = tid >> 3;            // batch 0..31

    // xw prefetch for step 0
    float xg[6];
    {
        const int t0 = dir ? (TLEN - 1) : 0;
        const float* xp = g_xw + ((size_t)t0 * NC + dir * 1536 + u0 + cu2 * 2) * BATCH
                          + B0 + cb;
        #pragma unroll
        for (int g = 0; g < 3; g++) {
            xg[g * 2]     = __ldg(xp + (size_t)g * 512 * BATCH);
            xg[g * 2 + 1] = __ldg(xp + ((size_t)g * 512 + 1) * BATCH);
        }
    }

    for (int s = 0; s < TLEN; s++) {
        const int p = s & 1;
        const int t = dir ? (TLEN - 1 - s) : s;

        const float* hbase = g_h + (size_t)(gid * 2 + p) * UNITS * BPG;

        // prefetch h_old for combine (L2 latency hidden under matvec)
        const float hold0 = __ldg(hbase + (u0 + cu2 * 2) * 32 + cb);
        const float hold1 = __ldg(hbase + (u0 + cu2 * 2 + 1) * 32 + cb);

        // matvec: 4 units x 4 batches x 3 gates over 64 k; h from L2, 8-deep
        ull az[2][4], ar[2][4], ah[2][4];
        #pragma unroll
        for (int i = 0; i < 2; i++)
            #pragma unroll
            for (int j = 0; j < 4; j++) { az[i][j] = ar[i][j] = ah[i][j] = 0ull; }
        {
            const float4* hp = (const float4*)(hbase + (size_t)kh * 64 * 32 + bg * 4);
            const float*  up = Us + (size_t)kh * 64 * 48 + uh * 4;
            #pragma unroll 1
            for (int kk = 0; kk < 64; kk += 8) {
                float4 hbuf[8];
                #pragma unroll
                for (int j = 0; j < 8; j++)
                    hbuf[j] = __ldg(hp + (size_t)(kk + j) * 8);
                #pragma unroll
                for (int j = 0; j < 8; j++) {
                    const float* uk = up + (size_t)(kk + j) * 48;
                    const ulonglong2 z2 = *(const ulonglong2*)(uk);
                    const ulonglong2 r2 = *(const ulonglong2*)(uk + 16);
                    const ulonglong2 q2 = *(const ulonglong2*)(uk + 32);
                    const ull hd[4] = {pk2(hbuf[j].x, hbuf[j].x),
                                       pk2(hbuf[j].y, hbuf[j].y),
                                       pk2(hbuf[j].z, hbuf[j].z),
                                       pk2(hbuf[j].w, hbuf[j].w)};
                    #pragma unroll
                    for (int b = 0; b < 4; b++) {
                        fma2(az[0][b], z2.x, hd[b]); fma2(az[1][b], z2.y, hd[b]);
                        fma2(ar[0][b], r2.x, hd[b]); fma2(ar[1][b], r2.y, hd[b]);
                        fma2(ah[0][b], q2.x, hd[b]); fma2(ah[1][b], q2.y, hd[b]);
                    }
                }
            }
        }
        // part[(kh*3+g)*576 + b*18 + u]
        {
            #pragma unroll
            for (int b = 0; b < 4; b++) {
                float* pb = part + kh * 3 * 576 + (bg * 4 + b) * 18 + uh * 4;
                *(ull*)(pb)            = az[0][b];
                *(ull*)(pb + 2)        = az[1][b];
                *(ull*)(pb + 576)      = ar[0][b];
                *(ull*)(pb + 576 + 2)  = ar[1][b];
                *(ull*)(pb + 1152)     = ah[0][b];
                *(ull*)(pb + 1152 + 2) = ah[1][b];
            }
        }
        __syncthreads();

        // combine: units cu2*2, cu2*2+1; batch cb
        float hn0, hn1;
        {
            float rz0 = brec[cu2 * 2],      rz1 = brec[cu2 * 2 + 1];
            float rr0 = brec[16 + cu2 * 2], rr1 = brec[16 + cu2 * 2 + 1];
            float rh0 = brec[32 + cu2 * 2], rh1 = brec[32 + cu2 * 2 + 1];
            #pragma unroll
            for (int q = 0; q < 8; q++) {
                const float* pq = part + q * 3 * 576 + cb * 18 + cu2 * 2;
                float2 v;
                v = upk2(*(const ull*)(pq));        rz0 += v.x; rz1 += v.y;
                v = upk2(*(const ull*)(pq + 576));  rr0 += v.x; rr1 += v.y;
                v = upk2(*(const ull*)(pq + 1152)); rh0 += v.x; rh1 += v.y;
            }
            const float z0 = 1.f / (1.f + expf(-(xg[0] + rz0)));
            const float z1 = 1.f / (1.f + expf(-(xg[1] + rz1)));
            const float r0 = 1.f / (1.f + expf(-(xg[2] + rr0)));
            const float r1 = 1.f / (1.f + expf(-(xg[3] + rr1)));
            const float c0 = tanhf(xg[4] + r0 * rh0);
            const float c1 = tanhf(xg[5] + r1 * rh1);
            hn0 = z0 * hold0 + (1.f - z0) * c0;
            hn1 = z1 * hold1 + (1.f - z1) * c1;

            float* hw = g_h + (size_t)(gid * 2 + (p ^ 1)) * UNITS * BPG;
            hw[(u0 + cu2 * 2) * 32 + cb]     = hn0;
            hw[(u0 + cu2 * 2 + 1) * 32 + cb] = hn1;
        }
        bar_arrive(gid, 32);   // h published

        // ---- latency cover between arrive and wait ----
        {
            float2 o2 = make_float2(hn0, hn1);
            *(float2*)(out + ((size_t)(B0 + cb) * TLEN + t) * 1024
                           + dir * 512 + u0 + cu2 * 2) = o2;
            if (s == TLEN - 1)
                *(float2*)(out + (size_t)BATCH * TLEN * 1024
                               + (size_t)(B0 + cb) * 1024
                               + dir * 512 + u0 + cu2 * 2) = o2;
        }
        if (s + 1 < TLEN) {   // prefetch xw for next step
            const int tn = dir ? (TLEN - 2 - s) : (s + 1);
            const float* xp = g_xw + ((size_t)tn * NC + dir * 1536 + u0 + cu2 * 2) * BATCH
                              + B0 + cb;
            #pragma unroll
            for (int g = 0; g < 3; g++) {
                xg[g * 2]     = __ldg(xp + (size_t)g * 512 * BATCH);
                xg[g * 2 + 1] = __ldg(xp + ((size_t)g * 512 + 1) * BATCH);
            }
        }
        bar_wait(gid, gen);
        gen++;
    }
}

// ---------------- launch ----------------------------------------------------
extern "C" void kernel_launch(void* const* d_in, const int* in_sizes, int n_in,
                              void* d_out, int out_size)
{
    const int*   tokens = (const int*)  d_in[0];
    const float* emb    = (const float*)d_in[1];
    const float* W_f    = (const float*)d_in[2];
    const float* U_f    = (const float*)d_in[3];
    const float* b_f    = (const float*)d_in[4];
    const float* W_b    = (const float*)d_in[5];
    const float* U_b    = (const float*)d_in[6];
    const float* b_b    = (const float*)d_in[7];
    float* out = (float*)d_out;

    (void)in_sizes; (void)n_in; (void)out_size;

    cudaFuncSetAttribute(embed_gemm, cudaFuncAttributeMaxDynamicSharedMemorySize,
                         EG_SMEM);
    dim3 g1(NC / 256, TLEN);
    embed_gemm<<<g1, 256, EG_SMEM>>>(tokens, emb, W_f, W_b, b_f, b_b);

    const size_t smem = (512 * 48 + 24 * 576) * sizeof(float); // 153600
    cudaFuncSetAttribute(gru_scan, cudaFuncAttributeMaxDynamicSharedMemorySize,
                         (int)smem);
    gru_scan<<<128, 256, smem>>>(U_f, U_b, b_f, b_b, out);
}